// round 14
// baseline (speedup 1.0000x reference)
#include <cuda_runtime.h>
#include <cuda_fp16.h>
#include <cstdint>

#define SEQ 2048
#define NB 2
#define ROWS (NB * SEQ)      // 4096 total (b,s) rows
#define HDIM 4096
#define NH 32
#define NKV 8
#define HD 128
#define QLD (NH * HD)        // 4096
#define KLD (NKV * HD)       // 1024
#define NBH (NB * NH)        // 64

// ---------------- scratch (static device allocations; no cudaMalloc) -------
__device__ __half g_hs16[(size_t)ROWS * HDIM];
__device__ __half g_wq16[(size_t)QLD * HDIM];
__device__ __half g_wk16[(size_t)KLD * HDIM];
__device__ __half g_wv16[(size_t)KLD * HDIM];
__device__ __half g_wo16[(size_t)HDIM * QLD];
__device__ __half g_q16[(size_t)ROWS * QLD];              // roped Q (scaled)
__device__ __half g_k16[(size_t)ROWS * KLD];              // roped K
__device__ __half g_v16t[(size_t)NB * KLD * SEQ];         // V transposed [b][kv][d][s]
__device__ __half g_attn16[(size_t)ROWS * QLD];           // flash out

// ---------------- helpers ---------------------------------------------------
__device__ __forceinline__ uint32_t smem_u32(const void* p) {
    uint32_t a;
    asm("{ .reg .u64 t; cvta.to.shared.u64 t, %1; cvt.u32.u64 %0, t; }" : "=r"(a) : "l"(p));
    return a;
}
__device__ __forceinline__ uint32_t packh2(float a, float b) {
    __half2 h = __floats2half2_rn(a, b);
    return *(uint32_t*)&h;
}

#define CP_ASYNC16(dst, src) \
    asm volatile("cp.async.cg.shared.global [%0], [%1], 16;" :: "r"(dst), "l"(src) : "memory")
#define CP_COMMIT() asm volatile("cp.async.commit_group;" ::: "memory")
#define CP_WAIT(n)  asm volatile("cp.async.wait_group %0;" :: "n"(n) : "memory")

#define LDSM4(r0, r1, r2, r3, addr) \
    asm volatile("ldmatrix.sync.aligned.m8n8.x4.shared.b16 {%0,%1,%2,%3}, [%4];" \
        : "=r"(r0), "=r"(r1), "=r"(r2), "=r"(r3) : "r"(addr))

// fp16 mma: 16x8x16, fp32 accumulate
__device__ __forceinline__ void mma16(float* c, const uint32_t* a, const uint32_t* b) {
    asm volatile(
        "mma.sync.aligned.m16n8k16.row.col.f32.f16.f16.f32 "
        "{%0,%1,%2,%3}, {%4,%5,%6,%7}, {%8,%9}, {%0,%1,%2,%3};\n"
        : "+f"(c[0]), "+f"(c[1]), "+f"(c[2]), "+f"(c[3])
        : "r"(a[0]), "r"(a[1]), "r"(a[2]), "r"(a[3]), "r"(b[0]), "r"(b[1]));
}

// ============================================================================
// Projection GEMM (fp16 operands): C[128,128] tile = A * B^T.
// A [M,K], B [N,K] row-major __half.  256 threads = 8 warps (4m x 2n),
// warp tile 32x64.  BK=64, 3-stage cp.async, 2 CTAs/SM (4 warps/SMSP),
// ldmatrix fragments.   (round-13 configuration — unchanged)
// MODE 0: fp32 C out (out_proj).
// MODE 1: V transposed fp16 out -> g_v16t.
// MODE 2: RoPE + scale + fp16 out -> g_q16 (tile cols = one head).
// MODE 3: RoPE + fp16 out -> g_k16.
// ============================================================================
#define HBK 64
#define HSTAGE 3
#define HSTR 72                                // halves (64 + 8 pad)
#define HT_BYTES (128 * HSTR * 2)              // 18432 per tile
#define HSTAGE_BYTES (2 * HT_BYTES)            // 36864
#define PSMEM_H (HSTAGE * HSTAGE_BYTES)        // 110592

template <int MODE>
__device__ __forceinline__ void pgemm_h(
    const __half* __restrict__ A, const __half* __restrict__ B, float* __restrict__ C,
    int m0, int n0, int K, int lda, int ldb, int ldc,
    const float* __restrict__ cosT, const float* __restrict__ sinT)
{
    extern __shared__ float dsm[];
    const uint32_t sbase = smem_u32(dsm);

    const int tid = threadIdx.x;
    const int arow = tid >> 3;          // 0..31 (rows arow + 32*i)
    const int ac = (tid & 7) << 3;      // 0,8,...,56 halves

    const int warp = tid >> 5;          // 0..7
    const int lane = tid & 31;
    const int wm = (warp & 3) << 5;     // 0,32,64,96
    const int wn = (warp >> 2) << 6;    // 0,64
    const int g  = lane >> 2;
    const int tg = lane & 3;

    const int lrA = (((lane >> 3) & 1) << 3) + (lane & 7);
    const int lkA = (lane >> 4) << 3;
    const int lrB = (((lane >> 4) & 1) << 3) + (lane & 7);
    const int lkB = ((lane >> 3) & 1) << 3;

    uint32_t offA[2], offB[4];
#pragma unroll
    for (int mt = 0; mt < 2; mt++)
        offA[mt] = (uint32_t)(((wm + mt * 16 + lrA) * HSTR + lkA) * 2);
#pragma unroll
    for (int np = 0; np < 4; np++)
        offB[np] = (uint32_t)(((wn + np * 16 + lrB) * HSTR + lkB) * 2) + HT_BYTES;

    float acc[2][8][4];
#pragma unroll
    for (int i = 0; i < 2; i++)
#pragma unroll
        for (int j = 0; j < 8; j++)
#pragma unroll
            for (int l = 0; l < 4; l++) acc[i][j][l] = 0.f;

    const int nk = K / HBK;

#define HLOAD(s) do {                                                              \
        const uint32_t sa_u = sbase + (uint32_t)((s) % HSTAGE) * HSTAGE_BYTES;     \
        const uint32_t sb_u = sa_u + HT_BYTES;                                     \
        const __half* pa_ = A + (size_t)(m0 + arow) * lda + (s) * HBK + ac;        \
        const __half* pb_ = B + (size_t)(n0 + arow) * ldb + (s) * HBK + ac;        \
        _Pragma("unroll")                                                          \
        for (int r_ = 0; r_ < 128; r_ += 32) {                                     \
            CP_ASYNC16(sa_u + (uint32_t)((arow + r_) * HSTR + ac) * 2u,            \
                       pa_ + (size_t)r_ * lda);                                    \
            CP_ASYNC16(sb_u + (uint32_t)((arow + r_) * HSTR + ac) * 2u,            \
                       pb_ + (size_t)r_ * ldb);                                    \
        }                                                                          \
    } while (0)

#pragma unroll
    for (int s = 0; s < HSTAGE - 1; s++) {
        if (s < nk) HLOAD(s);
        CP_COMMIT();
    }

    for (int kt = 0; kt < nk; kt++) {
        CP_WAIT(HSTAGE - 2);
        __syncthreads();
        if (kt + HSTAGE - 1 < nk) HLOAD(kt + HSTAGE - 1);
        CP_COMMIT();

        const uint32_t st_u = sbase + (uint32_t)((kt % HSTAGE) * HSTAGE_BYTES);

#pragma unroll
        for (int ks = 0; ks < 4; ks++) {       // four k16 steps per 64-k tile
            const uint32_t kadd = ks * 32;     // +16 halves
            uint32_t af[2][4];
#pragma unroll
            for (int mt = 0; mt < 2; mt++)
                LDSM4(af[mt][0], af[mt][1], af[mt][2], af[mt][3],
                      st_u + offA[mt] + kadd);
            uint32_t bf[8][2];
#pragma unroll
            for (int np = 0; np < 4; np++)
                LDSM4(bf[2 * np][0], bf[2 * np][1], bf[2 * np + 1][0], bf[2 * np + 1][1],
                      st_u + offB[np] + kadd);
#pragma unroll
            for (int mt = 0; mt < 2; mt++)
#pragma unroll
                for (int nt = 0; nt < 8; nt++)
                    mma16(acc[mt][nt], af[mt], bf[nt]);
        }
        __syncthreads();
    }

    if (MODE == 0 || MODE == 1) {
#pragma unroll
        for (int mt = 0; mt < 2; mt++) {
            const int r = m0 + wm + mt * 16 + g;
#pragma unroll
            for (int nt = 0; nt < 8; nt++) {
                const int c = n0 + wn + nt * 8 + (tg << 1);
                const float v0 = acc[mt][nt][0], v1 = acc[mt][nt][1];
                const float v2 = acc[mt][nt][2], v3 = acc[mt][nt][3];
                if (MODE == 0) {
                    float* p0 = C + (size_t)r * ldc + c;
                    *(float2*)p0 = make_float2(v0, v1);
                    float* p1 = p0 + (size_t)8 * ldc;
                    *(float2*)p1 = make_float2(v2, v3);
                } else {
                    const int b = r >> 11, s = r & (SEQ - 1);
                    const size_t base = ((size_t)b * KLD + c) * SEQ + s;
                    g_v16t[base]           = __float2half_rn(v0);
                    g_v16t[base + SEQ]     = __float2half_rn(v1);
                    g_v16t[base + 8]       = __float2half_rn(v2);
                    g_v16t[base + SEQ + 8] = __float2half_rn(v3);
                }
            }
        }
    } else {
        // ---- RoPE epilogue: stage fp32 tile in smem, mix (d, d+64), emit fp16
        float* sm = dsm;   // 128 x 132 fp32 tile (67.6 KB <= PSMEM_H)
#pragma unroll
        for (int mt = 0; mt < 2; mt++) {
            const int r = wm + mt * 16 + g;
#pragma unroll
            for (int nt = 0; nt < 8; nt++) {
                const int c = wn + nt * 8 + (tg << 1);
                *(float2*)&sm[r * 132 + c]       = make_float2(acc[mt][nt][0], acc[mt][nt][1]);
                *(float2*)&sm[(r + 8) * 132 + c] = make_float2(acc[mt][nt][2], acc[mt][nt][3]);
            }
        }
        __syncthreads();

        const float scq = (MODE == 2) ? 0.08838834764831845f : 1.0f;
        __half* outb = (MODE == 2) ? g_q16 : g_k16;
        const int ldo = (MODE == 2) ? QLD : KLD;

#pragma unroll
        for (int i = 0; i < 16; i++) {
            const int idx = tid + i * 256;       // 0..4095
            const int row = idx >> 5;            // 0..127
            const int dd = (idx & 31) << 1;      // 0,2,...,62
            const int rg = m0 + row;
            const int s = rg & (SEQ - 1);
            const float2 x1 = *(const float2*)&sm[row * 132 + dd];
            const float2 x2 = *(const float2*)&sm[row * 132 + dd + 64];
            const float2 c1 = *(const float2*)&cosT[(size_t)s * HD + dd];
            const float2 s1 = *(const float2*)&sinT[(size_t)s * HD + dd];
            const float2 c2 = *(const float2*)&cosT[(size_t)s * HD + dd + 64];
            const float2 s2 = *(const float2*)&sinT[(size_t)s * HD + dd + 64];
            __half* ob = outb + (size_t)rg * ldo + n0 + dd;
            *(__half2*)ob = __floats2half2_rn((x1.x * c1.x - x2.x * s1.x) * scq,
                                              (x1.y * c1.y - x2.y * s1.y) * scq);
            *(__half2*)(ob + 64) = __floats2half2_rn((x2.x * c2.x + x1.x * s2.x) * scq,
                                                     (x2.y * c2.y + x1.y * s2.y) * scq);
        }
    }
#undef HLOAD
}

// ---------------- projection wrappers ----------------------------------------
// merged QKV: grid (48, 32); x: [0,32)->Q(rope), [32,40)->K(rope), [40,48)->V(transpose)
__global__ void __launch_bounds__(256, 2) k_proj_qkv(const float* __restrict__ cosT,
                                                     const float* __restrict__ sinT) {
    const int nb = blockIdx.x;
    const int m0 = blockIdx.y * 128;
    if (nb < 32) {
        pgemm_h<2>(g_hs16, g_wq16, nullptr, m0, nb * 128, HDIM, HDIM, HDIM, 0, cosT, sinT);
    } else if (nb < 40) {
        pgemm_h<3>(g_hs16, g_wk16, nullptr, m0, (nb - 32) * 128, HDIM, HDIM, HDIM, 0, cosT, sinT);
    } else {
        pgemm_h<1>(g_hs16, g_wv16, nullptr, m0, (nb - 40) * 128, HDIM, HDIM, HDIM, 0, nullptr, nullptr);
    }
}
__global__ void __launch_bounds__(256, 2) k_out_proj(float* __restrict__ out) {
    pgemm_h<0>(g_attn16, g_wo16, out, blockIdx.y * 128, blockIdx.x * 128,
               QLD, QLD, HDIM, HDIM, nullptr, nullptr);
}

// ============================================================================
// Fused flash attention (causal, online softmax), fp16 mma, ldmatrix frags.
// Grid (16 q-blocks [reversed], 64 z).  256 threads = 8 warps, 16 Q rows each.
// Q pre-scaled by 1/sqrt(HD).  V read transposed from g_v16t.
// 3-stage KV pipeline, ONE barrier per KV tile (load issued after barrier;
// barrier at iter t guarantees reads of buffer (t-1)%3 = (t+2)%3 are done).
// ============================================================================
#define KSTRW 68                    // K/Q smem row stride words (136 halves, 272B)
#define VSTRW 36                    // V^T row stride words (72 halves, 144B)
#define K_TILE_W (64 * KSTRW)       // 4352 words
#define V_TILE_W (128 * VSTRW)      // 4608 words
#define FSTAGE 3
#define FSMEM (FSTAGE * (K_TILE_W + V_TILE_W) * 4)   // 107520 bytes

__global__ void __launch_bounds__(256, 1) k_flash() {
    extern __shared__ uint32_t fsm[];
    const uint32_t sbase = smem_u32(fsm);

    const int tid = threadIdx.x;
    const int wid = tid >> 5, lane = tid & 31;
    const int g = lane >> 2, tg = lane & 3;
    const int wm = wid * 16;

    const int z = blockIdx.y, b = z >> 5, h = z & 31, kvh = h >> 2;
    const int qb = (int)(gridDim.x - 1 - blockIdx.x);
    const int q0 = qb * 128;
    const int nkv = 2 * qb + 2;

    const __half* Qp = g_q16 + (size_t)(b * SEQ + q0) * QLD + h * HD;
    const __half* Kp = g_k16 + (size_t)b * SEQ * KLD + kvh * HD;
    const __half* Vt = g_v16t + (size_t)(b * NKV + kvh) * HD * SEQ;

    const int lrB = (((lane >> 4) & 1) << 3) + (lane & 7);
    const int lkB = ((lane >> 3) & 1) << 3;
    const int lrA = (((lane >> 3) & 1) << 3) + (lane & 7);
    const int lkA = (lane >> 4) << 3;

    // ---- stage Q tile (128 rows x 128 halves, 272B rows) over K stages 0-1
#pragma unroll
    for (int i = 0; i < 8; i++) {
        const int op = tid + i * 256;
        const int row = op >> 4, ch = op & 15;
        CP_ASYNC16(sbase + (uint32_t)(row * 272 + ch * 16), Qp + (size_t)row * QLD + ch * 8);
    }
    CP_COMMIT();
    CP_WAIT(0);
    __syncthreads();

    uint32_t qf[8][4];
    {
        const uint32_t qoff = sbase + (uint32_t)((wm + lrA) * 272 + lkA * 2);
#pragma unroll
        for (int ks = 0; ks < 8; ks++)
            LDSM4(qf[ks][0], qf[ks][1], qf[ks][2], qf[ks][3], qoff + ks * 32);
    }
    __syncthreads();

    uint32_t kbu[FSTAGE], vbu[FSTAGE];
#pragma unroll
    for (int s = 0; s < FSTAGE; s++) {
        kbu[s] = sbase + (uint32_t)(s * K_TILE_W * 4);
        vbu[s] = sbase + (uint32_t)((FSTAGE * K_TILE_W + s * V_TILE_W) * 4);
    }

    uint32_t offK[4], offV[8];
#pragma unroll
    for (int np = 0; np < 4; np++)
        offK[np] = (uint32_t)((np * 16 + lrB) * 272 + lkB * 2);
#pragma unroll
    for (int np = 0; np < 8; np++)
        offV[np] = (uint32_t)((np * 16 + lrB) * 144 + lkB * 2);

#define LOAD_KV(t) do {                                                          \
        const int kv0_ = (t) * 64, p_ = (t) % FSTAGE;                            \
        _Pragma("unroll")                                                        \
        for (int i_ = 0; i_ < 4; i_++) {                                         \
            const int op_ = tid + i_ * 256;                                      \
            const int krow_ = op_ >> 4, kch_ = op_ & 15;                         \
            CP_ASYNC16(kbu[p_] + (uint32_t)(krow_ * 272 + kch_ * 16),            \
                       Kp + (size_t)(kv0_ + krow_) * KLD + kch_ * 8);            \
            const int vrow_ = op_ >> 3, vch_ = op_ & 7;                          \
            CP_ASYNC16(vbu[p_] + (uint32_t)(vrow_ * 144 + vch_ * 16),            \
                       Vt + (size_t)vrow_ * SEQ + kv0_ + vch_ * 8);              \
        }                                                                        \
        CP_COMMIT();                                                             \
    } while (0)

    LOAD_KV(0);
    LOAD_KV(1);

    float mrow0 = -1e30f, mrow1 = -1e30f;
    float lrow0 = 0.f, lrow1 = 0.f;
    float o[16][4];
#pragma unroll
    for (int i = 0; i < 16; i++)
#pragma unroll
        for (int j = 0; j < 4; j++) o[i][j] = 0.f;

    const int r0g = q0 + wm + g, r1g = r0g + 8;

    for (int t = 0; t < nkv; t++) {
        const int p = t % FSTAGE, kv0 = t * 64;
        if (t + 1 < nkv) { CP_WAIT(1); } else { CP_WAIT(0); }
        __syncthreads();                    // single barrier per KV tile
        if (t + 2 < nkv) LOAD_KV(t + 2);

        float sacc[8][4];
#pragma unroll
        for (int nt = 0; nt < 8; nt++)
#pragma unroll
            for (int j = 0; j < 4; j++) sacc[nt][j] = 0.f;

#pragma unroll
        for (int ks = 0; ks < 8; ks++) {
            uint32_t bf[8][2];
#pragma unroll
            for (int np = 0; np < 4; np++)
                LDSM4(bf[2 * np][0], bf[2 * np][1], bf[2 * np + 1][0], bf[2 * np + 1][1],
                      kbu[p] + offK[np] + ks * 32);
#pragma unroll
            for (int nt = 0; nt < 8; nt++)
                mma16(sacc[nt], qf[ks], bf[nt]);
        }

        float mnew0 = mrow0, mnew1 = mrow1;
        const bool domask = (kv0 + 63 > q0);
#pragma unroll
        for (int nt = 0; nt < 8; nt++) {
            const int c0 = kv0 + nt * 8 + 2 * tg, c1 = c0 + 1;
            float v0 = sacc[nt][0], v1 = sacc[nt][1];
            float v2 = sacc[nt][2], v3 = sacc[nt][3];
            if (domask) {
                if (c0 > r0g) v0 = -1e30f;
                if (c1 > r0g) v1 = -1e30f;
                if (c0 > r1g) v2 = -1e30f;
                if (c1 > r1g) v3 = -1e30f;
            }
            sacc[nt][0] = v0; sacc[nt][1] = v1; sacc[nt][2] = v2; sacc[nt][3] = v3;
            mnew0 = fmaxf(mnew0, fmaxf(v0, v1));
            mnew1 = fmaxf(mnew1, fmaxf(v2, v3));
        }
        mnew0 = fmaxf(mnew0, __shfl_xor_sync(0xffffffffu, mnew0, 1));
        mnew0 = fmaxf(mnew0, __shfl_xor_sync(0xffffffffu, mnew0, 2));
        mnew1 = fmaxf(mnew1, __shfl_xor_sync(0xffffffffu, mnew1, 1));
        mnew1 = fmaxf(mnew1, __shfl_xor_sync(0xffffffffu, mnew1, 2));

        const float f0 = __expf(mrow0 - mnew0);
        const float f1 = __expf(mrow1 - mnew1);

        float rs0 = 0.f, rs1 = 0.f;
#pragma unroll
        for (int nt = 0; nt < 8; nt++) {
            const float e0 = __expf(sacc[nt][0] - mnew0);
            const float e1 = __expf(sacc[nt][1] - mnew0);
            const float e2 = __expf(sacc[nt][2] - mnew1);
            const float e3 = __expf(sacc[nt][3] - mnew1);
            sacc[nt][0] = e0; sacc[nt][1] = e1; sacc[nt][2] = e2; sacc[nt][3] = e3;
            rs0 += e0 + e1;
            rs1 += e2 + e3;
        }
        rs0 += __shfl_xor_sync(0xffffffffu, rs0, 1);
        rs0 += __shfl_xor_sync(0xffffffffu, rs0, 2);
        rs1 += __shfl_xor_sync(0xffffffffu, rs1, 1);
        rs1 += __shfl_xor_sync(0xffffffffu, rs1, 2);

        lrow0 = lrow0 * f0 + rs0;
        lrow1 = lrow1 * f1 + rs1;
        mrow0 = mnew0;
        mrow1 = mnew1;

#pragma unroll
        for (int nt2 = 0; nt2 < 16; nt2++) {
            o[nt2][0] *= f0; o[nt2][1] *= f0;
            o[nt2][2] *= f1; o[nt2][3] *= f1;
        }

#pragma unroll
        for (int ks2 = 0; ks2 < 4; ks2++) {
            uint32_t pa[4];
            pa[0] = packh2(sacc[2 * ks2][0],     sacc[2 * ks2][1]);
            pa[1] = packh2(sacc[2 * ks2][2],     sacc[2 * ks2][3]);
            pa[2] = packh2(sacc[2 * ks2 + 1][0], sacc[2 * ks2 + 1][1]);
            pa[3] = packh2(sacc[2 * ks2 + 1][2], sacc[2 * ks2 + 1][3]);
            uint32_t vf[16][2];
#pragma unroll
            for (int np = 0; np < 8; np++)
                LDSM4(vf[2 * np][0], vf[2 * np][1], vf[2 * np + 1][0], vf[2 * np + 1][1],
                      vbu[p] + offV[np] + ks2 * 32);
#pragma unroll
            for (int nt2 = 0; nt2 < 16; nt2++)
                mma16(o[nt2], pa, vf[nt2]);
        }
    }

    const float inv0 = 1.f / lrow0;
    const float inv1 = 1.f / lrow1;
    __half* orow0 = g_attn16 + (size_t)(b * SEQ + r0g) * QLD + h * HD;
    __half* orow1 = g_attn16 + (size_t)(b * SEQ + r1g) * QLD + h * HD;
#pragma unroll
    for (int nt2 = 0; nt2 < 16; nt2++) {
        const int c = nt2 * 8 + 2 * tg;
        *(__half2*)(orow0 + c) = __floats2half2_rn(o[nt2][0] * inv0, o[nt2][1] * inv0);
        *(__half2*)(orow1 + c) = __floats2half2_rn(o[nt2][2] * inv1, o[nt2][3] * inv1);
    }
#undef LOAD_KV
}

// ---------------- merged fp32 -> fp16 prepass (one launch, 1 uint4/thread) ---
__device__ __forceinline__ void cvt8(uint4* __restrict__ dst,
                                     const float4* __restrict__ src, size_t oi) {
    const float4 a = src[2 * oi];
    const float4 b = src[2 * oi + 1];
    __half2 h0 = __floats2half2_rn(a.x, a.y);
    __half2 h1 = __floats2half2_rn(a.z, a.w);
    __half2 h2 = __floats2half2_rn(b.x, b.y);
    __half2 h3 = __floats2half2_rn(b.z, b.w);
    uint4 o;
    o.x = *(uint32_t*)&h0;
    o.y = *(uint32_t*)&h1;
    o.z = *(uint32_t*)&h2;
    o.w = *(uint32_t*)&h3;
    dst[oi] = o;
}

#define N_BIG ((size_t)ROWS * HDIM / 8)   // 2M uint4 outputs (hs, wq, wo)
#define N_SML ((size_t)KLD * HDIM / 8)    // 512K uint4 outputs (wk, wv)
#define CVT_TOTAL (3 * N_BIG + 2 * N_SML) // 7340032
#define CVT_BLOCKS (CVT_TOTAL / 256)      // 28672

__global__ void cvt_all(const float4* __restrict__ hs, const float4* __restrict__ wq,
                        const float4* __restrict__ wk, const float4* __restrict__ wv,
                        const float4* __restrict__ wo) {
    size_t i = (size_t)blockIdx.x * 256 + threadIdx.x;
    if (i < N_BIG) { cvt8((uint4*)g_hs16, hs, i); return; }
    i -= N_BIG;
    if (i < N_BIG) { cvt8((uint4*)g_wq16, wq, i); return; }
    i -= N_BIG;
    if (i < N_SML) { cvt8((uint4*)g_wk16, wk, i); return; }
    i -= N_SML;
    if (i < N_SML) { cvt8((uint4*)g_wv16, wv, i); return; }
    i -= N_SML;
    cvt8((uint4*)g_wo16, wo, i);
}

// ---------------- launch -----------------------------------------------------
extern "C" void kernel_launch(void* const* d_in, const int* in_sizes, int n_in,
                              void* d_out, int out_size) {
    (void)in_sizes; (void)n_in; (void)out_size;
    const float* hs   = (const float*)d_in[0];
    const float* Wq   = (const float*)d_in[1];
    const float* Wk   = (const float*)d_in[2];
    const float* Wv   = (const float*)d_in[3];
    const float* Wo   = (const float*)d_in[4];
    const float* cosT = (const float*)d_in[5];
    const float* sinT = (const float*)d_in[6];
    float* out = (float*)d_out;

    static bool attr_set = false;
    if (!attr_set) {
        cudaFuncSetAttribute(k_proj_qkv, cudaFuncAttributeMaxDynamicSharedMemorySize, PSMEM_H);
        cudaFuncSetAttribute(k_out_proj, cudaFuncAttributeMaxDynamicSharedMemorySize, PSMEM_H);
        cudaFuncSetAttribute(k_flash,    cudaFuncAttributeMaxDynamicSharedMemorySize, FSMEM);
        attr_set = true;
    }

    cvt_all<<<(unsigned)CVT_BLOCKS, 256>>>((const float4*)hs, (const float4*)Wq,
                                           (const float4*)Wk, (const float4*)Wv,
                                           (const float4*)Wo);
    k_proj_qkv<<<dim3(48, ROWS / 128), 256, PSMEM_H>>>(cosT, sinT);
    k_flash<<<dim3(SEQ / 128, NBH), 256, FSMEM>>>();
    k_out_proj<<<dim3(HDIM / 128, ROWS / 128), 256, PSMEM_H>>>(out);
}

// round 15
// speedup vs baseline: 1.0275x; 1.0275x over previous
#include <cuda_runtime.h>
#include <cuda_fp16.h>
#include <cstdint>

#define SEQ 2048
#define NB 2
#define ROWS (NB * SEQ)      // 4096 total (b,s) rows
#define HDIM 4096
#define NH 32
#define NKV 8
#define HD 128
#define QLD (NH * HD)        // 4096
#define KLD (NKV * HD)       // 1024
#define NBH (NB * NH)        // 64

// ---------------- scratch (static device allocations; no cudaMalloc) -------
__device__ __half g_hs16[(size_t)ROWS * HDIM];
__device__ __half g_wq16[(size_t)QLD * HDIM];
__device__ __half g_wk16[(size_t)KLD * HDIM];
__device__ __half g_wv16[(size_t)KLD * HDIM];
__device__ __half g_wo16[(size_t)HDIM * QLD];
__device__ __half g_q16[(size_t)ROWS * QLD];              // roped Q (scaled)
__device__ __half g_k16[(size_t)ROWS * KLD];              // roped K
__device__ __half g_v16t[(size_t)NB * KLD * SEQ];         // V transposed [b][kv][d][s]
__device__ __half g_attn16[(size_t)ROWS * QLD];           // flash out

// ---------------- helpers ---------------------------------------------------
__device__ __forceinline__ uint32_t smem_u32(const void* p) {
    uint32_t a;
    asm("{ .reg .u64 t; cvta.to.shared.u64 t, %1; cvt.u32.u64 %0, t; }" : "=r"(a) : "l"(p));
    return a;
}
__device__ __forceinline__ uint32_t packh2(float a, float b) {
    __half2 h = __floats2half2_rn(a, b);
    return *(uint32_t*)&h;
}

#define CP_ASYNC16(dst, src) \
    asm volatile("cp.async.cg.shared.global [%0], [%1], 16;" :: "r"(dst), "l"(src) : "memory")
#define CP_COMMIT() asm volatile("cp.async.commit_group;" ::: "memory")
#define CP_WAIT(n)  asm volatile("cp.async.wait_group %0;" :: "n"(n) : "memory")

#define LDSM4(r0, r1, r2, r3, addr) \
    asm volatile("ldmatrix.sync.aligned.m8n8.x4.shared.b16 {%0,%1,%2,%3}, [%4];" \
        : "=r"(r0), "=r"(r1), "=r"(r2), "=r"(r3) : "r"(addr))

// fp16 mma: 16x8x16, fp32 accumulate
__device__ __forceinline__ void mma16(float* c, const uint32_t* a, const uint32_t* b) {
    asm volatile(
        "mma.sync.aligned.m16n8k16.row.col.f32.f16.f16.f32 "
        "{%0,%1,%2,%3}, {%4,%5,%6,%7}, {%8,%9}, {%0,%1,%2,%3};\n"
        : "+f"(c[0]), "+f"(c[1]), "+f"(c[2]), "+f"(c[3])
        : "r"(a[0]), "r"(a[1]), "r"(a[2]), "r"(a[3]), "r"(b[0]), "r"(b[1]));
}

// ============================================================================
// Projection GEMM (fp16 operands): C[128,128] tile = A * B^T.
// A [M,K], B [N,K] row-major __half.  256 threads = 8 warps (4m x 2n),
// warp tile 32x64.  BK=64, 3-stage cp.async, 2 CTAs/SM (4 warps/SMSP),
// ldmatrix fragments.  SINGLE barrier per k-tile (safe: top barrier at iter kt
// proves all warps finished iter kt-1 reads; HLOAD(kt+2) hits stage (kt-1)%3).
// MODE 0: fp32 C out (out_proj).
// MODE 1: V transposed fp16 out -> g_v16t.
// MODE 2: RoPE + scale + fp16 out -> g_q16 (tile cols = one head).
// MODE 3: RoPE + fp16 out -> g_k16.
// ============================================================================
#define HBK 64
#define HSTAGE 3
#define HSTR 72                                // halves (64 + 8 pad)
#define HT_BYTES (128 * HSTR * 2)              // 18432 per tile
#define HSTAGE_BYTES (2 * HT_BYTES)            // 36864
#define PSMEM_H (HSTAGE * HSTAGE_BYTES)        // 110592

template <int MODE>
__device__ __forceinline__ void pgemm_h(
    const __half* __restrict__ A, const __half* __restrict__ B, float* __restrict__ C,
    int m0, int n0, int K, int lda, int ldb, int ldc,
    const float* __restrict__ cosT, const float* __restrict__ sinT)
{
    extern __shared__ float dsm[];
    const uint32_t sbase = smem_u32(dsm);

    const int tid = threadIdx.x;
    const int arow = tid >> 3;          // 0..31 (rows arow + 32*i)
    const int ac = (tid & 7) << 3;      // 0,8,...,56 halves

    const int warp = tid >> 5;          // 0..7
    const int lane = tid & 31;
    const int wm = (warp & 3) << 5;     // 0,32,64,96
    const int wn = (warp >> 2) << 6;    // 0,64
    const int g  = lane >> 2;
    const int tg = lane & 3;

    const int lrA = (((lane >> 3) & 1) << 3) + (lane & 7);
    const int lkA = (lane >> 4) << 3;
    const int lrB = (((lane >> 4) & 1) << 3) + (lane & 7);
    const int lkB = ((lane >> 3) & 1) << 3;

    uint32_t offA[2], offB[4];
#pragma unroll
    for (int mt = 0; mt < 2; mt++)
        offA[mt] = (uint32_t)(((wm + mt * 16 + lrA) * HSTR + lkA) * 2);
#pragma unroll
    for (int np = 0; np < 4; np++)
        offB[np] = (uint32_t)(((wn + np * 16 + lrB) * HSTR + lkB) * 2) + HT_BYTES;

    float acc[2][8][4];
#pragma unroll
    for (int i = 0; i < 2; i++)
#pragma unroll
        for (int j = 0; j < 8; j++)
#pragma unroll
            for (int l = 0; l < 4; l++) acc[i][j][l] = 0.f;

    const int nk = K / HBK;

#define HLOAD(s) do {                                                              \
        const uint32_t sa_u = sbase + (uint32_t)((s) % HSTAGE) * HSTAGE_BYTES;     \
        const uint32_t sb_u = sa_u + HT_BYTES;                                     \
        const __half* pa_ = A + (size_t)(m0 + arow) * lda + (s) * HBK + ac;        \
        const __half* pb_ = B + (size_t)(n0 + arow) * ldb + (s) * HBK + ac;        \
        _Pragma("unroll")                                                          \
        for (int r_ = 0; r_ < 128; r_ += 32) {                                     \
            CP_ASYNC16(sa_u + (uint32_t)((arow + r_) * HSTR + ac) * 2u,            \
                       pa_ + (size_t)r_ * lda);                                    \
            CP_ASYNC16(sb_u + (uint32_t)((arow + r_) * HSTR + ac) * 2u,            \
                       pb_ + (size_t)r_ * ldb);                                    \
        }                                                                          \
    } while (0)

#pragma unroll
    for (int s = 0; s < HSTAGE - 1; s++) {
        if (s < nk) HLOAD(s);
        CP_COMMIT();
    }

    for (int kt = 0; kt < nk; kt++) {
        CP_WAIT(HSTAGE - 2);
        __syncthreads();                       // single barrier per k-tile
        if (kt + HSTAGE - 1 < nk) HLOAD(kt + HSTAGE - 1);
        CP_COMMIT();

        const uint32_t st_u = sbase + (uint32_t)((kt % HSTAGE) * HSTAGE_BYTES);

#pragma unroll
        for (int ks = 0; ks < 4; ks++) {       // four k16 steps per 64-k tile
            const uint32_t kadd = ks * 32;     // +16 halves
            uint32_t af[2][4];
#pragma unroll
            for (int mt = 0; mt < 2; mt++)
                LDSM4(af[mt][0], af[mt][1], af[mt][2], af[mt][3],
                      st_u + offA[mt] + kadd);
            uint32_t bf[8][2];
#pragma unroll
            for (int np = 0; np < 4; np++)
                LDSM4(bf[2 * np][0], bf[2 * np][1], bf[2 * np + 1][0], bf[2 * np + 1][1],
                      st_u + offB[np] + kadd);
#pragma unroll
            for (int mt = 0; mt < 2; mt++)
#pragma unroll
                for (int nt = 0; nt < 8; nt++)
                    mma16(acc[mt][nt], af[mt], bf[nt]);
        }
    }

    if (MODE == 0 || MODE == 1) {
#pragma unroll
        for (int mt = 0; mt < 2; mt++) {
            const int r = m0 + wm + mt * 16 + g;
#pragma unroll
            for (int nt = 0; nt < 8; nt++) {
                const int c = n0 + wn + nt * 8 + (tg << 1);
                const float v0 = acc[mt][nt][0], v1 = acc[mt][nt][1];
                const float v2 = acc[mt][nt][2], v3 = acc[mt][nt][3];
                if (MODE == 0) {
                    float* p0 = C + (size_t)r * ldc + c;
                    *(float2*)p0 = make_float2(v0, v1);
                    float* p1 = p0 + (size_t)8 * ldc;
                    *(float2*)p1 = make_float2(v2, v3);
                } else {
                    const int b = r >> 11, s = r & (SEQ - 1);
                    const size_t base = ((size_t)b * KLD + c) * SEQ + s;
                    g_v16t[base]           = __float2half_rn(v0);
                    g_v16t[base + SEQ]     = __float2half_rn(v1);
                    g_v16t[base + 8]       = __float2half_rn(v2);
                    g_v16t[base + SEQ + 8] = __float2half_rn(v3);
                }
            }
        }
    } else {
        // ---- RoPE epilogue: stage fp32 tile in smem, mix (d, d+64), emit fp16
        __syncthreads();   // slow warps may still read pipeline stage fragments
        float* sm = dsm;   // 128 x 132 fp32 tile (67.6 KB <= PSMEM_H)
#pragma unroll
        for (int mt = 0; mt < 2; mt++) {
            const int r = wm + mt * 16 + g;
#pragma unroll
            for (int nt = 0; nt < 8; nt++) {
                const int c = wn + nt * 8 + (tg << 1);
                *(float2*)&sm[r * 132 + c]       = make_float2(acc[mt][nt][0], acc[mt][nt][1]);
                *(float2*)&sm[(r + 8) * 132 + c] = make_float2(acc[mt][nt][2], acc[mt][nt][3]);
            }
        }
        __syncthreads();

        const float scq = (MODE == 2) ? 0.08838834764831845f : 1.0f;
        __half* outb = (MODE == 2) ? g_q16 : g_k16;
        const int ldo = (MODE == 2) ? QLD : KLD;

#pragma unroll
        for (int i = 0; i < 16; i++) {
            const int idx = tid + i * 256;       // 0..4095
            const int row = idx >> 5;            // 0..127
            const int dd = (idx & 31) << 1;      // 0,2,...,62
            const int rg = m0 + row;
            const int s = rg & (SEQ - 1);
            const float2 x1 = *(const float2*)&sm[row * 132 + dd];
            const float2 x2 = *(const float2*)&sm[row * 132 + dd + 64];
            const float2 c1 = *(const float2*)&cosT[(size_t)s * HD + dd];
            const float2 s1 = *(const float2*)&sinT[(size_t)s * HD + dd];
            const float2 c2 = *(const float2*)&cosT[(size_t)s * HD + dd + 64];
            const float2 s2 = *(const float2*)&sinT[(size_t)s * HD + dd + 64];
            __half* ob = outb + (size_t)rg * ldo + n0 + dd;
            *(__half2*)ob = __floats2half2_rn((x1.x * c1.x - x2.x * s1.x) * scq,
                                              (x1.y * c1.y - x2.y * s1.y) * scq);
            *(__half2*)(ob + 64) = __floats2half2_rn((x2.x * c2.x + x1.x * s2.x) * scq,
                                                     (x2.y * c2.y + x1.y * s2.y) * scq);
        }
    }
#undef HLOAD
}

// ---------------- projection wrappers ----------------------------------------
// merged QKV: grid (48, 32); x: [0,32)->Q(rope), [32,40)->K(rope), [40,48)->V(transpose)
__global__ void __launch_bounds__(256, 2) k_proj_qkv(const float* __restrict__ cosT,
                                                     const float* __restrict__ sinT) {
    const int nb = blockIdx.x;
    const int m0 = blockIdx.y * 128;
    if (nb < 32) {
        pgemm_h<2>(g_hs16, g_wq16, nullptr, m0, nb * 128, HDIM, HDIM, HDIM, 0, cosT, sinT);
    } else if (nb < 40) {
        pgemm_h<3>(g_hs16, g_wk16, nullptr, m0, (nb - 32) * 128, HDIM, HDIM, HDIM, 0, cosT, sinT);
    } else {
        pgemm_h<1>(g_hs16, g_wv16, nullptr, m0, (nb - 40) * 128, HDIM, HDIM, HDIM, 0, nullptr, nullptr);
    }
}
__global__ void __launch_bounds__(256, 2) k_out_proj(float* __restrict__ out) {
    pgemm_h<0>(g_attn16, g_wo16, out, blockIdx.y * 128, blockIdx.x * 128,
               QLD, QLD, HDIM, HDIM, nullptr, nullptr);
}

// ============================================================================
// Fused flash attention (causal, online softmax), fp16 mma, ldmatrix frags.
// Grid (16 q-blocks [reversed], 64 z).  256 threads = 8 warps, 16 Q rows each.
// Q pre-scaled by 1/sqrt(HD).  V read transposed from g_v16t.
// (round-13 configuration: 2-stage KV, two barriers per tile)
// ============================================================================
#define KSTRW 68                    // K/Q smem row stride words (136 halves, 272B)
#define VSTRW 36                    // V^T row stride words (72 halves, 144B)
#define K_TILE_W (64 * KSTRW)       // 4352 words
#define V_TILE_W (128 * VSTRW)      // 4608 words
#define FSMEM ((2 * K_TILE_W + 2 * V_TILE_W) * 4)   // 71680 bytes

__global__ void __launch_bounds__(256, 1) k_flash() {
    extern __shared__ uint32_t fsm[];
    const uint32_t sbase = smem_u32(fsm);

    const int tid = threadIdx.x;
    const int wid = tid >> 5, lane = tid & 31;
    const int g = lane >> 2, tg = lane & 3;
    const int wm = wid * 16;

    const int z = blockIdx.y, b = z >> 5, h = z & 31, kvh = h >> 2;
    const int qb = (int)(gridDim.x - 1 - blockIdx.x);
    const int q0 = qb * 128;
    const int nkv = 2 * qb + 2;

    const __half* Qp = g_q16 + (size_t)(b * SEQ + q0) * QLD + h * HD;
    const __half* Kp = g_k16 + (size_t)b * SEQ * KLD + kvh * HD;
    const __half* Vt = g_v16t + (size_t)(b * NKV + kvh) * HD * SEQ;

    const int lrB = (((lane >> 4) & 1) << 3) + (lane & 7);
    const int lkB = ((lane >> 3) & 1) << 3;
    const int lrA = (((lane >> 3) & 1) << 3) + (lane & 7);
    const int lkA = (lane >> 4) << 3;

    // ---- stage Q tile (128 rows x 128 halves, 272B rows)
#pragma unroll
    for (int i = 0; i < 8; i++) {
        const int op = tid + i * 256;
        const int row = op >> 4, ch = op & 15;
        CP_ASYNC16(sbase + (uint32_t)(row * 272 + ch * 16), Qp + (size_t)row * QLD + ch * 8);
    }
    CP_COMMIT();
    CP_WAIT(0);
    __syncthreads();

    uint32_t qf[8][4];
    {
        const uint32_t qoff = sbase + (uint32_t)((wm + lrA) * 272 + lkA * 2);
#pragma unroll
        for (int ks = 0; ks < 8; ks++)
            LDSM4(qf[ks][0], qf[ks][1], qf[ks][2], qf[ks][3], qoff + ks * 32);
    }
    __syncthreads();

    const uint32_t kbu[2] = { sbase, sbase + K_TILE_W * 4u };
    const uint32_t vbu[2] = { sbase + 2u * K_TILE_W * 4u,
                              sbase + 2u * K_TILE_W * 4u + V_TILE_W * 4u };

    uint32_t offK[4], offV[8];
#pragma unroll
    for (int np = 0; np < 4; np++)
        offK[np] = (uint32_t)((np * 16 + lrB) * 272 + lkB * 2);
#pragma unroll
    for (int np = 0; np < 8; np++)
        offV[np] = (uint32_t)((np * 16 + lrB) * 144 + lkB * 2);

#define LOAD_KV(t) do {                                                          \
        const int kv0_ = (t) * 64, p_ = (t) & 1;                                 \
        _Pragma("unroll")                                                        \
        for (int i_ = 0; i_ < 4; i_++) {                                         \
            const int op_ = tid + i_ * 256;                                      \
            const int krow_ = op_ >> 4, kch_ = op_ & 15;                         \
            CP_ASYNC16(kbu[p_] + (uint32_t)(krow_ * 272 + kch_ * 16),            \
                       Kp + (size_t)(kv0_ + krow_) * KLD + kch_ * 8);            \
            const int vrow_ = op_ >> 3, vch_ = op_ & 7;                          \
            CP_ASYNC16(vbu[p_] + (uint32_t)(vrow_ * 144 + vch_ * 16),            \
                       Vt + (size_t)vrow_ * SEQ + kv0_ + vch_ * 8);              \
        }                                                                        \
        CP_COMMIT();                                                             \
    } while (0)

    LOAD_KV(0);
    LOAD_KV(1);

    float mrow0 = -1e30f, mrow1 = -1e30f;
    float lrow0 = 0.f, lrow1 = 0.f;
    float o[16][4];
#pragma unroll
    for (int i = 0; i < 16; i++)
#pragma unroll
        for (int j = 0; j < 4; j++) o[i][j] = 0.f;

    const int r0g = q0 + wm + g, r1g = r0g + 8;

    for (int t = 0; t < nkv; t++) {
        const int p = t & 1, kv0 = t * 64;
        if (t + 1 < nkv) { CP_WAIT(1); } else { CP_WAIT(0); }
        __syncthreads();

        float sacc[8][4];
#pragma unroll
        for (int nt = 0; nt < 8; nt++)
#pragma unroll
            for (int j = 0; j < 4; j++) sacc[nt][j] = 0.f;

#pragma unroll
        for (int ks = 0; ks < 8; ks++) {
            uint32_t bf[8][2];
#pragma unroll
            for (int np = 0; np < 4; np++)
                LDSM4(bf[2 * np][0], bf[2 * np][1], bf[2 * np + 1][0], bf[2 * np + 1][1],
                      kbu[p] + offK[np] + ks * 32);
#pragma unroll
            for (int nt = 0; nt < 8; nt++)
                mma16(sacc[nt], qf[ks], bf[nt]);
        }

        float mnew0 = mrow0, mnew1 = mrow1;
        const bool domask = (kv0 + 63 > q0);
#pragma unroll
        for (int nt = 0; nt < 8; nt++) {
            const int c0 = kv0 + nt * 8 + 2 * tg, c1 = c0 + 1;
            float v0 = sacc[nt][0], v1 = sacc[nt][1];
            float v2 = sacc[nt][2], v3 = sacc[nt][3];
            if (domask) {
                if (c0 > r0g) v0 = -1e30f;
                if (c1 > r0g) v1 = -1e30f;
                if (c0 > r1g) v2 = -1e30f;
                if (c1 > r1g) v3 = -1e30f;
            }
            sacc[nt][0] = v0; sacc[nt][1] = v1; sacc[nt][2] = v2; sacc[nt][3] = v3;
            mnew0 = fmaxf(mnew0, fmaxf(v0, v1));
            mnew1 = fmaxf(mnew1, fmaxf(v2, v3));
        }
        mnew0 = fmaxf(mnew0, __shfl_xor_sync(0xffffffffu, mnew0, 1));
        mnew0 = fmaxf(mnew0, __shfl_xor_sync(0xffffffffu, mnew0, 2));
        mnew1 = fmaxf(mnew1, __shfl_xor_sync(0xffffffffu, mnew1, 1));
        mnew1 = fmaxf(mnew1, __shfl_xor_sync(0xffffffffu, mnew1, 2));

        const float f0 = __expf(mrow0 - mnew0);
        const float f1 = __expf(mrow1 - mnew1);

        float rs0 = 0.f, rs1 = 0.f;
#pragma unroll
        for (int nt = 0; nt < 8; nt++) {
            const float e0 = __expf(sacc[nt][0] - mnew0);
            const float e1 = __expf(sacc[nt][1] - mnew0);
            const float e2 = __expf(sacc[nt][2] - mnew1);
            const float e3 = __expf(sacc[nt][3] - mnew1);
            sacc[nt][0] = e0; sacc[nt][1] = e1; sacc[nt][2] = e2; sacc[nt][3] = e3;
            rs0 += e0 + e1;
            rs1 += e2 + e3;
        }
        rs0 += __shfl_xor_sync(0xffffffffu, rs0, 1);
        rs0 += __shfl_xor_sync(0xffffffffu, rs0, 2);
        rs1 += __shfl_xor_sync(0xffffffffu, rs1, 1);
        rs1 += __shfl_xor_sync(0xffffffffu, rs1, 2);

        lrow0 = lrow0 * f0 + rs0;
        lrow1 = lrow1 * f1 + rs1;
        mrow0 = mnew0;
        mrow1 = mnew1;

#pragma unroll
        for (int nt2 = 0; nt2 < 16; nt2++) {
            o[nt2][0] *= f0; o[nt2][1] *= f0;
            o[nt2][2] *= f1; o[nt2][3] *= f1;
        }

#pragma unroll
        for (int ks2 = 0; ks2 < 4; ks2++) {
            uint32_t pa[4];
            pa[0] = packh2(sacc[2 * ks2][0],     sacc[2 * ks2][1]);
            pa[1] = packh2(sacc[2 * ks2][2],     sacc[2 * ks2][3]);
            pa[2] = packh2(sacc[2 * ks2 + 1][0], sacc[2 * ks2 + 1][1]);
            pa[3] = packh2(sacc[2 * ks2 + 1][2], sacc[2 * ks2 + 1][3]);
            uint32_t vf[16][2];
#pragma unroll
            for (int np = 0; np < 8; np++)
                LDSM4(vf[2 * np][0], vf[2 * np][1], vf[2 * np + 1][0], vf[2 * np + 1][1],
                      vbu[p] + offV[np] + ks2 * 32);
#pragma unroll
            for (int nt2 = 0; nt2 < 16; nt2++)
                mma16(o[nt2], pa, vf[nt2]);
        }

        __syncthreads();
        if (t + 2 < nkv) LOAD_KV(t + 2);
    }

    const float inv0 = 1.f / lrow0;
    const float inv1 = 1.f / lrow1;
    __half* orow0 = g_attn16 + (size_t)(b * SEQ + r0g) * QLD + h * HD;
    __half* orow1 = g_attn16 + (size_t)(b * SEQ + r1g) * QLD + h * HD;
#pragma unroll
    for (int nt2 = 0; nt2 < 16; nt2++) {
        const int c = nt2 * 8 + 2 * tg;
        *(__half2*)(orow0 + c) = __floats2half2_rn(o[nt2][0] * inv0, o[nt2][1] * inv0);
        *(__half2*)(orow1 + c) = __floats2half2_rn(o[nt2][2] * inv1, o[nt2][3] * inv1);
    }
#undef LOAD_KV
}

// ---------------- merged fp32 -> fp16 prepass (one launch, 1 uint4/thread) ---
__device__ __forceinline__ void cvt8(uint4* __restrict__ dst,
                                     const float4* __restrict__ src, size_t oi) {
    const float4 a = src[2 * oi];
    const float4 b = src[2 * oi + 1];
    __half2 h0 = __floats2half2_rn(a.x, a.y);
    __half2 h1 = __floats2half2_rn(a.z, a.w);
    __half2 h2 = __floats2half2_rn(b.x, b.y);
    __half2 h3 = __floats2half2_rn(b.z, b.w);
    uint4 o;
    o.x = *(uint32_t*)&h0;
    o.y = *(uint32_t*)&h1;
    o.z = *(uint32_t*)&h2;
    o.w = *(uint32_t*)&h3;
    dst[oi] = o;
}

#define N_BIG ((size_t)ROWS * HDIM / 8)   // 2M uint4 outputs (hs, wq, wo)
#define N_SML ((size_t)KLD * HDIM / 8)    // 512K uint4 outputs (wk, wv)
#define CVT_TOTAL (3 * N_BIG + 2 * N_SML) // 7340032
#define CVT_BLOCKS (CVT_TOTAL / 256)      // 28672

__global__ void cvt_all(const float4* __restrict__ hs, const float4* __restrict__ wq,
                        const float4* __restrict__ wk, const float4* __restrict__ wv,
                        const float4* __restrict__ wo) {
    size_t i = (size_t)blockIdx.x * 256 + threadIdx.x;
    if (i < N_BIG) { cvt8((uint4*)g_hs16, hs, i); return; }
    i -= N_BIG;
    if (i < N_BIG) { cvt8((uint4*)g_wq16, wq, i); return; }
    i -= N_BIG;
    if (i < N_SML) { cvt8((uint4*)g_wk16, wk, i); return; }
    i -= N_SML;
    if (i < N_SML) { cvt8((uint4*)g_wv16, wv, i); return; }
    i -= N_SML;
    cvt8((uint4*)g_wo16, wo, i);
}

// ---------------- launch -----------------------------------------------------
extern "C" void kernel_launch(void* const* d_in, const int* in_sizes, int n_in,
                              void* d_out, int out_size) {
    (void)in_sizes; (void)n_in; (void)out_size;
    const float* hs   = (const float*)d_in[0];
    const float* Wq   = (const float*)d_in[1];
    const float* Wk   = (const float*)d_in[2];
    const float* Wv   = (const float*)d_in[3];
    const float* Wo   = (const float*)d_in[4];
    const float* cosT = (const float*)d_in[5];
    const float* sinT = (const float*)d_in[6];
    float* out = (float*)d_out;

    static bool attr_set = false;
    if (!attr_set) {
        cudaFuncSetAttribute(k_proj_qkv, cudaFuncAttributeMaxDynamicSharedMemorySize, PSMEM_H);
        cudaFuncSetAttribute(k_out_proj, cudaFuncAttributeMaxDynamicSharedMemorySize, PSMEM_H);
        cudaFuncSetAttribute(k_flash,    cudaFuncAttributeMaxDynamicSharedMemorySize, FSMEM);
        attr_set = true;
    }

    cvt_all<<<(unsigned)CVT_BLOCKS, 256>>>((const float4*)hs, (const float4*)Wq,
                                           (const float4*)Wk, (const float4*)Wv,
                                           (const float4*)Wo);
    k_proj_qkv<<<dim3(48, ROWS / 128), 256, PSMEM_H>>>(cosT, sinT);
    k_flash<<<dim3(SEQ / 128, NBH), 256, FSMEM>>>();
    k_out_proj<<<dim3(HDIM / 128, ROWS / 128), 256, PSMEM_H>>>(out);
}